// round 15
// baseline (speedup 1.0000x reference)
#include <cuda_runtime.h>
#include <cuda_bf16.h>

// Chamfer distance matrix, B=32, G=64, N=32, C=3.
// R15: double-evaluation with BOTH directions packed and zero cross-lane ops
// in the loop. dir-1: lane = row n, packed f32x2 over the g2-pair (operands
// from pair-packed s2). dir-2: lane = column m, packed f32x2 over the
// g1-PAIR (operands from pair-packed s1p) — the R4 splat-MOV overhead is
// gone because s1 is staged pre-packed. Each direction folds its
// lane-constant norm AFTER the min, so every chain is exactly 3 FFMA2.
// Per warp-iter (4 combos): 4 LDS + 12 fma + 8 FMNMX  (R10: 34 slots with
// 4 REDUX@rt4 on the alu pipe; this: ~26 slots, no REDUX).
// Block = (b, g1-pair, g2-quarter), warp = 1 g2-pair, (256,4), grid 4096.

#define NP 32

typedef unsigned long long u64;

static __device__ __forceinline__ u64 pack2(float lo, float hi) {
    u64 r; asm("mov.b64 %0, {%1, %2};" : "=l"(r) : "f"(lo), "f"(hi)); return r;
}
static __device__ __forceinline__ float2 unpack2(u64 v) {
    float2 f; asm("mov.b64 {%0, %1}, %2;" : "=f"(f.x), "=f"(f.y) : "l"(v)); return f;
}
static __device__ __forceinline__ u64 fma2(u64 a, u64 b, u64 c) {
    u64 d; asm("fma.rn.f32x2 %0, %1, %2, %3;" : "=l"(d) : "l"(a), "l"(b), "l"(c)); return d;
}
static __device__ __forceinline__ u64 add2(u64 a, u64 b) {
    u64 d; asm("add.rn.f32x2 %0, %1, %2;" : "=l"(d) : "l"(a), "l"(b)); return d;
}

__global__ __launch_bounds__(256, 4)
void chamfer_matrix_kernel(const float* __restrict__ x1,
                           const float* __restrict__ x2,
                           float* __restrict__ out)
{
    // Pair-packed x2 subset (this block's g2-quarter = 8 pairs):
    //   s2a[p*32+t] = {a.x,b.x, a.y,b.y}; s2b[p*32+t] = {a.z,b.z, a.w,b.w}
    __shared__ ulonglong2 s2a[8 * NP];      // 4 KB
    __shared__ ulonglong2 s2b[8 * NP];      // 4 KB
    // Pair-packed x1 g1-pair: s1a[t] = {Ax,Bx, Ay,By}; s1b[t] = {Az,Bz, Aw,Bw}
    __shared__ ulonglong2 s1a[NP];          // 0.5 KB
    __shared__ ulonglong2 s1b[NP];          // 0.5 KB

    const int blk = blockIdx.x;         // ((b*32 + gp)*4 + q)
    const int b   = blk >> 7;
    const int gp  = (blk >> 2) & 31;    // g1 pair -> groups 2gp, 2gp+1
    const int q   = blk & 3;            // g2 quarter -> groups [q*16, q*16+16)
    const int tid = threadIdx.x;
    const int g1A = b * 64 + 2 * gp;

    // Stage this block's 512 x2 points, pre-packed pairwise.
    const float* __restrict__ x2b = x2 + (size_t)(b * 64 + q * 16) * NP * 3;
    #pragma unroll
    for (int i = tid; i < 16 * NP; i += 256) {
        const float X = x2b[i * 3 + 0];
        const float Y = x2b[i * 3 + 1];
        const float Z = x2b[i * 3 + 2];
        const float W = fmaf(X, X, fmaf(Y, Y, Z * Z));
        const int g = i >> 5, m = i & 31;       // local group 0..15
        const int p = g >> 1, h = g & 1;        // local pair 0..7
        float* da = (float*)&s2a[p * NP + m];
        float* db = (float*)&s2b[p * NP + m];
        da[0 + h] = X;  da[2 + h] = Y;
        db[0 + h] = Z;  db[2 + h] = W;
    }
    // Stage the two x1 groups, pre-packed over the g1 pair.
    if (tid < 2 * NP) {
        const int h = tid >> 5, m = tid & 31;   // h: 0=A, 1=B
        const float* __restrict__ p = x1 + (size_t)((g1A + h) * NP + m) * 3;
        const float X = p[0], Y = p[1], Z = p[2];
        const float W = fmaf(X, X, fmaf(Y, Y, Z * Z));
        float* da = (float*)&s1a[m];
        float* db = (float*)&s1b[m];
        da[0 + h] = X;  da[2 + h] = Y;
        db[0 + h] = Z;  db[2 + h] = W;
    }

    const int wid  = tid >> 5;
    const int lane = tid & 31;

    // dir-1 lane-own x1 points (row n = lane), from gmem (L2-hot).
    const float* __restrict__ pA = x1 + (size_t)(g1A * NP + lane) * 3;
    const float* __restrict__ pB = pA + (size_t)NP * 3;
    const float xA = pA[0], yA = pA[1], zA = pA[2];
    const float xB = pB[0], yB = pB[1], zB = pB[2];
    const float wAs = fmaf(xA, xA, fmaf(yA, yA, zA * zA));
    const float wBs = fmaf(xB, xB, fmaf(yB, yB, zB * zB));
    const u64 pxA = pack2(-2.0f * xA, -2.0f * xA);
    const u64 pyA = pack2(-2.0f * yA, -2.0f * yA);
    const u64 pzA = pack2(-2.0f * zA, -2.0f * zA);
    const u64 pxB = pack2(-2.0f * xB, -2.0f * xB);
    const u64 pyB = pack2(-2.0f * yB, -2.0f * yB);
    const u64 pzB = pack2(-2.0f * zB, -2.0f * zB);

    __syncthreads();

    // dir-2 lane-own x2 point pair (column m = lane) from staged smem.
    const ulonglong2* __restrict__ q2a = &s2a[wid * NP];
    const ulonglong2* __restrict__ q2b = &s2b[wid * NP];
    u64 s0x, s0y, s0z, s1x, s1y, s1z;   // -2x splats per g2 group
    float w20, w21;                      // x2 norms at this lane per g2 group
    {
        const ulonglong2 va = q2a[lane], vb = q2b[lane];
        const float2 uxy = unpack2(va.x);   // {ax, bx}
        const float2 uyy = unpack2(va.y);   // {ay, by}
        const float2 uzz = unpack2(vb.x);   // {az, bz}
        const float2 uww = unpack2(vb.y);   // {aw, bw}
        s0x = pack2(-2.0f * uxy.x, -2.0f * uxy.x);
        s0y = pack2(-2.0f * uyy.x, -2.0f * uyy.x);
        s0z = pack2(-2.0f * uzz.x, -2.0f * uzz.x);
        s1x = pack2(-2.0f * uxy.y, -2.0f * uxy.y);
        s1y = pack2(-2.0f * uyy.y, -2.0f * uyy.y);
        s1z = pack2(-2.0f * uzz.y, -2.0f * uzz.y);
        w20 = uww.x;  w21 = uww.y;
    }

    const float FLTMAX = 3.402823466e+38f;
    // dir-1 row mins: m1[g1][g2]. dir-2 column mins: c[g2][g1].
    float m1A0 = FLTMAX, m1A1 = FLTMAX, m1B0 = FLTMAX, m1B1 = FLTMAX;
    float c0A = FLTMAX, c0B = FLTMAX, c1A = FLTMAX, c1B = FLTMAX;

    #pragma unroll 4
    for (int t = 0; t < NP; t++) {
        // dir-1: d'[lane][t] = w2[t] - 2<x1[lane], x2[t]>, packed over g2 pair.
        const ulonglong2 va = q2a[t];    // {ax,bx, ay,by}  broadcast LDS.128
        const ulonglong2 vb = q2b[t];    // {az,bz, aw,bw}  broadcast LDS.128
        const float2 fA = unpack2(fma2(pxA, va.x, fma2(pyA, va.y, fma2(pzA, vb.x, vb.y))));
        const float2 fB = unpack2(fma2(pxB, va.x, fma2(pyB, va.y, fma2(pzB, vb.x, vb.y))));
        m1A0 = fminf(m1A0, fA.x);  m1A1 = fminf(m1A1, fA.y);
        m1B0 = fminf(m1B0, fB.x);  m1B1 = fminf(m1B1, fB.y);

        // dir-2: d'[t][lane] = w1[t] - 2<x2[lane], x1[t]>, packed over g1 pair.
        const ulonglong2 ra = s1a[t];    // {Ax,Bx, Ay,By}  broadcast LDS.128
        const ulonglong2 rb = s1b[t];    // {Az,Bz, Aw,Bw}  broadcast LDS.128
        const float2 e0 = unpack2(fma2(s0x, ra.x, fma2(s0y, ra.y, fma2(s0z, rb.x, rb.y))));
        const float2 e1 = unpack2(fma2(s1x, ra.x, fma2(s1y, ra.y, fma2(s1z, rb.x, rb.y))));
        c0A = fminf(c0A, e0.x);  c0B = fminf(c0B, e0.y);
        c1A = fminf(c1A, e1.x);  c1B = fminf(c1B, e1.y);
    }

    // Epilogue: fold lane-constant norms, 4 packed butterfly sums.
    // dir-1 sums S1[g1][g2]; dir-2 sums S2[g2][g1]; out = (S1 + S2^T)/32.
    u64 v1 = pack2(m1A0 + wAs, m1A1 + wAs);     // (A,0),(A,1) dir-1
    u64 v2 = pack2(m1B0 + wBs, m1B1 + wBs);     // (B,0),(B,1) dir-1
    u64 v3 = pack2(c0A + w20, c1A + w21);       // (A,0),(A,1) dir-2 (transposed)
    u64 v4 = pack2(c0B + w20, c1B + w21);       // (B,0),(B,1) dir-2 (transposed)
    #pragma unroll
    for (int o = 16; o; o >>= 1) {
        v1 = add2(v1, __shfl_xor_sync(0xffffffffu, v1, o));
        v2 = add2(v2, __shfl_xor_sync(0xffffffffu, v2, o));
        v3 = add2(v3, __shfl_xor_sync(0xffffffffu, v3, o));
        v4 = add2(v4, __shfl_xor_sync(0xffffffffu, v4, o));
    }
    if (lane == 0) {
        const float2 r1 = unpack2(v1);
        const float2 r2 = unpack2(v2);
        const float2 r3 = unpack2(v3);
        const float2 r4 = unpack2(v4);
        const int g2 = q * 16 + wid * 2;
        out[(size_t)g1A * 64 + g2]           = (r1.x + r3.x) * (1.0f / 32.0f);
        out[(size_t)g1A * 64 + g2 + 1]       = (r1.y + r3.y) * (1.0f / 32.0f);
        out[(size_t)(g1A + 1) * 64 + g2]     = (r2.x + r4.x) * (1.0f / 32.0f);
        out[(size_t)(g1A + 1) * 64 + g2 + 1] = (r2.y + r4.y) * (1.0f / 32.0f);
    }
}

extern "C" void kernel_launch(void* const* d_in, const int* in_sizes, int n_in,
                              void* d_out, int out_size) {
    const float* x1  = (const float*)d_in[0];  // xyz1_matrix [32,64,32,3]
    const float* x2  = (const float*)d_in[1];  // xyz2_matrix [32,64,32,3]
    float*       out = (float*)d_out;          // [32,64,64]
    chamfer_matrix_kernel<<<32 * 32 * 4, 256>>>(x1, x2, out);
}

// round 16
// speedup vs baseline: 1.2665x; 1.2665x over previous
#include <cuda_runtime.h>
#include <cuda_bf16.h>

// Chamfer distance matrix, B=32, G=64, N=32, C=3.
// R16: R10 structure exactly (single-evaluation tile, broadcast LDS,
// lane-local row mins via FMNMX, s32-redux column mins, packed f32x2 over
// the g2 pair, (256,4) = 32 warps/SM, grid 4096) with unroll width 8.
// Design-space summary (R11-R15): fma and alu pipes are balanced at
// ~24 SMSP-cyc/warp-iter in this decomposition; every op-moving variant
// (systolic shfl, transposed recompute, hybrids) loses on one pipe.
// Remaining lever is issue efficiency around the REDUX/LDS latency chains;
// unroll 8 widens ptxas's interleaving window (unroll 4 and 32 measured,
// 8 untried).

#define NP 32

typedef unsigned long long u64;

static __device__ __forceinline__ u64 pack2(float lo, float hi) {
    u64 r; asm("mov.b64 %0, {%1, %2};" : "=l"(r) : "f"(lo), "f"(hi)); return r;
}
static __device__ __forceinline__ float2 unpack2(u64 v) {
    float2 f; asm("mov.b64 {%0, %1}, %2;" : "=f"(f.x), "=f"(f.y) : "l"(v)); return f;
}
static __device__ __forceinline__ u64 fma2(u64 a, u64 b, u64 c) {
    u64 d; asm("fma.rn.f32x2 %0, %1, %2, %3;" : "=l"(d) : "l"(a), "l"(b), "l"(c)); return d;
}
static __device__ __forceinline__ u64 add2(u64 a, u64 b) {
    u64 d; asm("add.rn.f32x2 %0, %1, %2;" : "=l"(d) : "l"(a), "l"(b)); return d;
}
// Warp-wide float min for non-negative floats via s32 redux on the bits.
static __device__ __forceinline__ float warp_min_pos(float v) {
    return __int_as_float(__reduce_min_sync(0xffffffffu, __float_as_int(v)));
}

__global__ __launch_bounds__(256, 4)
void chamfer_matrix_kernel(const float* __restrict__ x1,
                           const float* __restrict__ x2,
                           float* __restrict__ out)
{
    // Pair-packed x2 subset (this block's g2-quarter = 8 pairs):
    //   s2a[p*32+m] = {a.x,b.x, a.y,b.y}; s2b[p*32+m] = {a.z,b.z, a.w,b.w}
    __shared__ ulonglong2 s2a[8 * NP];      // 4 KB
    __shared__ ulonglong2 s2b[8 * NP];      // 4 KB

    const int blk = blockIdx.x;         // ((b*32 + gp)*4 + q)
    const int b   = blk >> 7;
    const int gp  = (blk >> 2) & 31;    // g1 pair -> groups 2gp, 2gp+1
    const int q   = blk & 3;            // g2 quarter -> groups [q*16, q*16+16)
    const int tid = threadIdx.x;

    // Stage this block's 512 x2 points, pre-packed pairwise.
    const float* __restrict__ x2b = x2 + (size_t)(b * 64 + q * 16) * NP * 3;
    #pragma unroll
    for (int i = tid; i < 16 * NP; i += 256) {
        const float X = x2b[i * 3 + 0];
        const float Y = x2b[i * 3 + 1];
        const float Z = x2b[i * 3 + 2];
        const float W = fmaf(X, X, fmaf(Y, Y, Z * Z));
        const int g = i >> 5, m = i & 31;       // local group 0..15
        const int p = g >> 1, h = g & 1;        // local pair 0..7
        float* da = (float*)&s2a[p * NP + m];
        float* db = (float*)&s2b[p * NP + m];
        da[0 + h] = X;  da[2 + h] = Y;
        db[0 + h] = Z;  db[2 + h] = W;
    }

    const int wid  = tid >> 5;
    const int lane = tid & 31;

    // Lane-own x1 points (groups 2gp, 2gp+1) straight from gmem (L2-hot).
    const int g1A = b * 64 + 2 * gp;
    const float* __restrict__ pA = x1 + (size_t)(g1A * NP + lane) * 3;
    const float* __restrict__ pB = pA + (size_t)NP * 3;
    const float xA = pA[0], yA = pA[1], zA = pA[2];
    const float xB = pB[0], yB = pB[1], zB = pB[2];
    const float wAs = fmaf(xA, xA, fmaf(yA, yA, zA * zA));
    const float wBs = fmaf(xB, xB, fmaf(yB, yB, zB * zB));

    // Pre-scaled (-2x) splats; norm splats for the in-loop bias.
    const u64 pxA = pack2(-2.0f * xA, -2.0f * xA);
    const u64 pyA = pack2(-2.0f * yA, -2.0f * yA);
    const u64 pzA = pack2(-2.0f * zA, -2.0f * zA);
    const u64 pxB = pack2(-2.0f * xB, -2.0f * xB);
    const u64 pyB = pack2(-2.0f * yB, -2.0f * yB);
    const u64 pzB = pack2(-2.0f * zB, -2.0f * zB);
    const u64 wA  = pack2(wAs, wAs);
    const u64 wB  = pack2(wBs, wBs);

    __syncthreads();

    const float FLTMAX = 3.402823466e+38f;
    float m1A0 = FLTMAX, m1A1 = FLTMAX, m1B0 = FLTMAX, m1B1 = FLTMAX;
    float sA0 = 0.0f, sA1 = 0.0f, sB0 = 0.0f, sB1 = 0.0f;

    // This warp's single g2-pair.
    const ulonglong2* __restrict__ q2a = &s2a[wid * NP];
    const ulonglong2* __restrict__ q2b = &s2b[wid * NP];

    #pragma unroll 8
    for (int m = 0; m < NP; m++) {
        const ulonglong2 va = q2a[m];   // {ax,bx, ay,by}  broadcast LDS.128
        const ulonglong2 vb = q2b[m];   // {az,bz, aw,bw}  broadcast LDS.128
        // Full distance d[n][m] (>= 0), both g2 groups of the pair:
        const u64 dA = fma2(pxA, va.x, fma2(pyA, va.y, fma2(pzA, vb.x, add2(vb.y, wA))));
        const u64 dB = fma2(pxB, va.x, fma2(pyB, va.y, fma2(pzB, vb.x, add2(vb.y, wB))));
        const float2 fA = unpack2(dA);
        const float2 fB = unpack2(dB);
        // dir-1: lane-local running min over m.
        m1A0 = fminf(m1A0, fA.x);  m1A1 = fminf(m1A1, fA.y);
        m1B0 = fminf(m1B0, fB.x);  m1B1 = fminf(m1B1, fB.y);
        // dir-2: exact warp-wide min over n (s32 redux on bits), sum over m.
        sA0 += warp_min_pos(fA.x);  sA1 += warp_min_pos(fA.y);
        sB0 += warp_min_pos(fB.x);  sB1 += warp_min_pos(fB.y);
    }

    // Epilogue: packed butterfly-sum of the dir-1 mins, add dir-2 sums.
    u64 vA = pack2(m1A0, m1A1);
    u64 vB = pack2(m1B0, m1B1);
    #pragma unroll
    for (int o = 16; o; o >>= 1) {
        vA = add2(vA, __shfl_xor_sync(0xffffffffu, vA, o));
        vB = add2(vB, __shfl_xor_sync(0xffffffffu, vB, o));
    }
    if (lane == 0) {
        const float2 rA = unpack2(vA);
        const float2 rB = unpack2(vB);
        const int g2 = q * 16 + wid * 2;
        out[(size_t)g1A * 64 + g2]           = (rA.x + sA0) * (1.0f / 32.0f);
        out[(size_t)g1A * 64 + g2 + 1]       = (rA.y + sA1) * (1.0f / 32.0f);
        out[(size_t)(g1A + 1) * 64 + g2]     = (rB.x + sB0) * (1.0f / 32.0f);
        out[(size_t)(g1A + 1) * 64 + g2 + 1] = (rB.y + sB1) * (1.0f / 32.0f);
    }
}

extern "C" void kernel_launch(void* const* d_in, const int* in_sizes, int n_in,
                              void* d_out, int out_size) {
    const float* x1  = (const float*)d_in[0];  // xyz1_matrix [32,64,32,3]
    const float* x2  = (const float*)d_in[1];  // xyz2_matrix [32,64,32,3]
    float*       out = (float*)d_out;          // [32,64,64]
    chamfer_matrix_kernel<<<32 * 32 * 4, 256>>>(x1, x2, out);
}